// round 13
// baseline (speedup 1.0000x reference)
#include <cuda_runtime.h>
#include <cuda_fp16.h>
#include <cstdint>

// MX (block-32, E8M0 scale, E4M3 elements) quantize-dequantize using the
// HARDWARE E4M3 converter (cvt.rn.satfinite.e4m3x2.f32 = RNE, sat at 448,
// E4M3 subnormals — exactly the reference semantics). Scales are exact
// powers of two from the block-amax exponent byte.
//
// Layout: each thread handles VPT=2 segments of 8 CONTIGUOUS floats (32 B),
// so stores can use st.global.L2::evict_last.v4.b64 (sm_103a requires 256-bit
// for evict_last). A warp covers 256 contiguous floats = 8 MX blocks; each
// block = 4 adjacent lanes -> reduction is just 2 x (shfl_xor + vmaxu4).
//
// Cache policy for the timed replay loop:
//   loads:  ld.global.cs (evict-first; 134MB input must not evict the output)
//   stores: L2::evict_last (output dirty lines stay L2-resident and are
//           overwritten by the next replay -> writeback traffic mostly gone)

#define VPT 2

__device__ __forceinline__ float2 qdq2(float a, float b, float inv_scale, float scale) {
    float sa = a * inv_scale;                // exact power-of-two multiply
    float sb = b * inv_scale;
    unsigned short q;
    asm("cvt.rn.satfinite.e4m3x2.f32 %0, %1, %2;" : "=h"(q) : "f"(sb), "f"(sa));
    unsigned hh;
    asm("cvt.rn.f16x2.e4m3x2 %0, %1;" : "=r"(hh) : "h"(q));
    __half2 h2 = *reinterpret_cast<__half2*>(&hh);
    float2 f = __half22float2(h2);           // exact widen
    f.x *= scale;                            // exact power-of-two multiply
    f.y *= scale;
    return f;
}

__device__ __forceinline__ unsigned long long pack64(float lo, float hi) {
    unsigned long long r;
    asm("mov.b64 %0, {%1, %2};" : "=l"(r) : "f"(lo), "f"(hi));
    return r;
}

__device__ __forceinline__ void st_evict_last32(float* p, const float* o) {
    unsigned long long q0 = pack64(o[0], o[1]);
    unsigned long long q1 = pack64(o[2], o[3]);
    unsigned long long q2 = pack64(o[4], o[5]);
    unsigned long long q3 = pack64(o[6], o[7]);
    asm volatile("st.global.L2::evict_last.v4.b64 [%0], {%1,%2,%3,%4};"
                 :: "l"(p), "l"(q0), "l"(q1), "l"(q2), "l"(q3) : "memory");
}

template <bool EXACT>
__global__ void __launch_bounds__(256) mx_qdq_kernel(const float* __restrict__ in,
                                                     float* __restrict__ out,
                                                     int n8) {
    int base = blockIdx.x * (256 * VPT) + threadIdx.x;   // segment index (8 floats each)

    // ---- front-batched streaming loads (MLP = 4 x LDG.128) ----
    float v[VPT][8];
#pragma unroll
    for (int j = 0; j < VPT; j++) {
        int seg = base + j * 256;
        if (EXACT || seg < n8) {
            const float4* src = (const float4*)(in + (size_t)seg * 8);
            float4 a = __ldcs(src);
            float4 b = __ldcs(src + 1);
            v[j][0]=a.x; v[j][1]=a.y; v[j][2]=a.z; v[j][3]=a.w;
            v[j][4]=b.x; v[j][5]=b.y; v[j][6]=b.z; v[j][7]=b.w;
        }
    }

    // ---- per-segment abs-bit max -> exponent byte, packed per-u32 ----
    unsigned p = 0u;
#pragma unroll
    for (int j = 0; j < VPT; j++) {
        unsigned a = 0u;
#pragma unroll
        for (int c = 0; c < 8; c++)
            a = max(a, __float_as_uint(v[j][c]) & 0x7FFFFFFFu);
        if (!EXACT && (base + j * 256) >= n8) a = 0u;
        p |= (a >> 23) << (8 * j);
    }

    // ---- 4-lane group reduction, byte-wise max (block = 4 adjacent lanes) ----
    p = __vmaxu4(p, __shfl_xor_sync(0xFFFFFFFFu, p, 1));
    p = __vmaxu4(p, __shfl_xor_sync(0xFFFFFFFFu, p, 2));

    // ---- HW-cvt quantize-dequantize + evict-last 256-bit store ----
#pragma unroll
    for (int j = 0; j < VPT; j++) {
        int seg = base + j * 256;
        if (!EXACT && seg >= n8) continue;

        // se = clip(floor(log2(amax)) - 8, -127, 127); E8M0 low clip via max(E,8).
        // Subnormal/zero amax clamps to se=-127 (all-zero block -> zeros anyway).
        unsigned mE = max((p >> (8 * j)) & 0xFFu, 8u);
        float inv_scale = __uint_as_float((262u - mE) << 23);            // 2^-se, always normal
        float scale = (mE > 8u) ? __uint_as_float((mE - 8u) << 23)       // 2^se
                                : __uint_as_float(0x00400000u);          // 2^-127 (subnormal)

        float o[8];
#pragma unroll
        for (int c = 0; c < 8; c += 2) {
            float2 r = qdq2(v[j][c], v[j][c + 1], inv_scale, scale);
            o[c] = r.x; o[c + 1] = r.y;
        }
        st_evict_last32(out + (size_t)seg * 8, o);
    }
}

extern "C" void kernel_launch(void* const* d_in, const int* in_sizes, int n_in,
                              void* d_out, int out_size) {
    const float* x = (const float*)d_in[0];
    float* out = (float*)d_out;
    int n = in_sizes[0];            // 4096*8192
    int n8 = n / 8;                 // 32B segments (n is a multiple of 8)
    const int per_block = 256 * VPT;
    if (n8 % per_block == 0) {
        mx_qdq_kernel<true><<<n8 / per_block, 256>>>(x, out, n8);
    } else {
        mx_qdq_kernel<false><<<(n8 + per_block - 1) / per_block, 256>>>(x, out, n8);
    }
}